// round 16
// baseline (speedup 1.0000x reference)
#include <cuda_runtime.h>
#include <cuda_bf16.h>
#include <cstdint>
#include <math.h>

// ---------------- device scratch (no allocations allowed) -------------------
__device__ float g_T[512 * 512];                               // sinusoidal table
__device__ __align__(16) __nv_bfloat16 g_xhi[16 * 512 * 32];   // x split hi
__device__ __align__(16) __nv_bfloat16 g_xlo[16 * 512 * 32];   // x split lo
__device__ __align__(16) __nv_bfloat16 g_WBhi[512 * 96];       // W d-major hi
__device__ __align__(16) __nv_bfloat16 g_WBlo[512 * 96];       // W d-major lo
__device__ int g_flag[512];                                    // per (b,n) nyquist-argmax flag

// ---------------- f32x2 packed helpers (K1) ---------------------------------
__device__ __forceinline__ unsigned long long pk2(float x, float y) {
    unsigned long long r;
    asm("mov.b64 %0, {%1,%2};" : "=l"(r) : "f"(x), "f"(y));
    return r;
}
__device__ __forceinline__ float2 up2(unsigned long long v) {
    float2 r;
    asm("mov.b64 {%0,%1}, %2;" : "=f"(r.x), "=f"(r.y) : "l"(v));
    return r;
}
__device__ __forceinline__ unsigned long long fma2(unsigned long long a,
                                                   unsigned long long b,
                                                   unsigned long long c) {
    unsigned long long d;
    asm("fma.rn.f32x2 %0, %1, %2, %3;" : "=l"(d) : "l"(a), "l"(b), "l"(c));
    return d;
}
__device__ __forceinline__ unsigned long long mul2(unsigned long long a,
                                                   unsigned long long b) {
    unsigned long long d;
    asm("mul.rn.f32x2 %0, %1, %2;" : "=l"(d) : "l"(a), "l"(b));
    return d;
}

// ---------------- warp-level bf16 HMMA (baseline PTX, compiles on sm_103) ----
__device__ __forceinline__ void mma16816(float& d0, float& d1, float& d2, float& d3,
                                         uint32_t a0, uint32_t a1, uint32_t a2, uint32_t a3,
                                         uint32_t b0, uint32_t b1) {
    asm volatile(
        "mma.sync.aligned.m16n8k16.row.col.f32.bf16.bf16.f32 "
        "{%0,%1,%2,%3}, {%4,%5,%6,%7}, {%8,%9}, {%0,%1,%2,%3};"
        : "+f"(d0), "+f"(d1), "+f"(d2), "+f"(d3)
        : "r"(a0), "r"(a1), "r"(a2), "r"(a3), "r"(b0), "r"(b1));
}

// ---------------- K0: table + bf16 splits + W permute ------------------------
// 512 blocks x 256 threads. Block r = table row; also converts x and W.
__global__ void setup_kernel(const float* __restrict__ x,
                             const float* __restrict__ conv_w) {
    int r = blockIdx.x;
    int j = threadIdx.x;
    float divf = exp2f((float)(-2 * j) * (13.2877123795494f / 512.0f));
    float ang = (float)r * divf;
    float s, c;
    sincosf(ang, &s, &c);
    g_T[r * 512 + 2 * j]     = s;
    g_T[r * 512 + 2 * j + 1] = c;
    // W permute + split: WB[d][tap*32+c] = conv_w[d*96 + c*3 + tap]
    if (j < 96) {
        float w = conv_w[r * 96 + (j & 31) * 3 + (j >> 5)];
        __nv_bfloat16 h = __float2bfloat16(w);
        g_WBhi[r * 96 + j] = h;
        g_WBlo[r * 96 + j] = __float2bfloat16(w - __bfloat162float(h));
    }
    // x split: pair p covers elements 2p, 2p+1
    int p = r * 256 + j;
    float2 xv = ((const float2*)x)[p];
    __nv_bfloat16 hx = __float2bfloat16(xv.x);
    __nv_bfloat16 hy = __float2bfloat16(xv.y);
    __nv_bfloat162 h2; h2.x = hx; h2.y = hy;
    __nv_bfloat162 l2;
    l2.x = __float2bfloat16(xv.x - __bfloat162float(hx));
    l2.y = __float2bfloat16(xv.y - __bfloat162float(hy));
    ((__nv_bfloat162*)g_xhi)[p] = h2;
    ((__nv_bfloat162*)g_xlo)[p] = l2;
}

// ---------------- K1: DFT argmax flags (race-free full write) ----------------
__global__ void __launch_bounds__(256) dft_kernel(const float* __restrict__ x) {
    __shared__ float xs[4][514];
    __shared__ float red[4][256];
    int blk = blockIdx.x;
    int b = blk >> 3;
    int n0 = (blk & 7) * 4;

    for (int i = threadIdx.x; i < 4 * 512; i += 256) {
        int s = i & 3, t = i >> 2;
        xs[s][t] = x[(b * 512 + t) * 32 + n0 + s];
    }
    __syncthreads();

    int k = threadIdx.x;
    float s1, c1, s2, c2;
    sincospif(-(float)k * (1.0f / 256.0f), &s1, &c1);
    sincospif(-(float)k * (1.0f / 128.0f), &s2, &c2);
    unsigned long long zr = pk2(1.0f, c1);
    unsigned long long zi = pk2(0.0f, s1);
    unsigned long long wr = pk2(c2, c2);
    unsigned long long wi = pk2(s2, s2);
    unsigned long long nwi = pk2(-s2, -s2);
    unsigned long long ar[4], ai[4];
#pragma unroll
    for (int s = 0; s < 4; ++s) { ar[s] = 0ULL; ai[s] = 0ULL; }

#pragma unroll 4
    for (int t2 = 0; t2 < 256; ++t2) {
        unsigned long long x0 = *(const unsigned long long*)&xs[0][2 * t2];
        unsigned long long x1 = *(const unsigned long long*)&xs[1][2 * t2];
        unsigned long long x2 = *(const unsigned long long*)&xs[2][2 * t2];
        unsigned long long x3 = *(const unsigned long long*)&xs[3][2 * t2];
        ar[0] = fma2(x0, zr, ar[0]); ai[0] = fma2(x0, zi, ai[0]);
        ar[1] = fma2(x1, zr, ar[1]); ai[1] = fma2(x1, zi, ai[1]);
        ar[2] = fma2(x2, zr, ar[2]); ai[2] = fma2(x2, zi, ai[2]);
        ar[3] = fma2(x3, zr, ar[3]); ai[3] = fma2(x3, zi, ai[3]);
        unsigned long long t0m = mul2(zr, wr);
        unsigned long long t1m = mul2(zr, wi);
        zr = fma2(zi, nwi, t0m);
        zi = fma2(zi, wr, t1m);
    }
#pragma unroll
    for (int s = 0; s < 4; ++s) {
        float2 ur = up2(ar[s]);
        float2 ui = up2(ai[s]);
        float re = ur.x + ur.y;
        float im = ui.x + ui.y;
        red[s][k] = re * re + im * im;
    }
    __syncthreads();

    int wid = threadIdx.x >> 5, lane = threadIdx.x & 31;
    if (wid < 4) {
        int s = wid;
        float acc = 0.0f;
#pragma unroll
        for (int j = 0; j < 16; ++j) acc += xs[s][lane + 32 * j];
        float v = (lane & 1) ? -acc : acc;
#pragma unroll
        for (int o = 16; o > 0; o >>= 1) v += __shfl_xor_sync(0xffffffffu, v, o);
        float nyq2 = v * v;
        float mx = 0.0f;
#pragma unroll
        for (int j = 0; j < 8; ++j) mx = fmaxf(mx, red[s][lane + 32 * j]);
#pragma unroll
        for (int o = 16; o > 0; o >>= 1)
            mx = fmaxf(mx, __shfl_xor_sync(0xffffffffu, mx, o));
        if (lane == 0) g_flag[b * 32 + n0 + s] = (nyq2 > mx) ? 1 : 0;
    }
}

// ---------------- K2: mma.sync bf16-split GEMM + fused epilogue --------------
// Block: D[128 t][64 d]; 4 warps, warp w owns rows [32w,32w+32) (2 m16 tiles).
// K = 96 = 6 chunks of 16; 3 bf16 products (hi*hi + lo*hi + hi*lo).
#define D_STRIDE 68   // floats; lane-conflict-free for float4 epilogue reads

__global__ void __launch_bounds__(128)
main_kernel(const int* __restrict__ xmark, float* __restrict__ out) {
    __shared__ float sD[128 * D_STRIDE];
    __shared__ int sCnt;

    int tid = threadIdx.x;
    int w = tid >> 5;
    int lane = tid & 31;
    int g = lane >> 2;        // group id 0..7 (row within 8)
    int tig = lane & 3;       // thread in group (k/col pairs)
    int b = blockIdx.z;
    int t0 = blockIdx.y * 128;
    int d0 = blockIdx.x * 64;

    // flags -> count for this b
    if (tid < 32) {
        int f = g_flag[b * 32 + tid];
        unsigned mask = __ballot_sync(0xffffffffu, f != 0);
        if (tid == 0) sCnt = __popc(mask);
    }

    float acc[2][8][4];
#pragma unroll
    for (int mt = 0; mt < 2; ++mt)
#pragma unroll
        for (int nt = 0; nt < 8; ++nt)
#pragma unroll
            for (int q = 0; q < 4; ++q) acc[mt][nt][q] = 0.0f;

    const __nv_bfloat16* xh = g_xhi + b * (512 * 32);
    const __nv_bfloat16* xl = g_xlo + b * (512 * 32);
    int rbase = t0 + w * 32 + g;   // + mt*16 (+8) per fragment row

    for (int kc = 0; kc < 6; ++kc) {
        int tap = kc >> 1;
        int cb = (kc & 1) * 16 + tig * 2;   // k-position of this thread's pair
        // ---- A fragments (hi, lo): rows rbase + {0,8,16,24}, cols cb, cb+8
        uint32_t ah[2][4], al[2][4];
#pragma unroll
        for (int mt = 0; mt < 2; ++mt) {
            int r0 = (rbase + mt * 16 + tap - 1) & 511;
            int r1 = (rbase + mt * 16 + 8 + tap - 1) & 511;
            const __nv_bfloat16* ph0 = xh + r0 * 32 + cb;
            const __nv_bfloat16* ph1 = xh + r1 * 32 + cb;
            const __nv_bfloat16* pl0 = xl + r0 * 32 + cb;
            const __nv_bfloat16* pl1 = xl + r1 * 32 + cb;
            ah[mt][0] = *(const uint32_t*)(ph0);
            ah[mt][1] = *(const uint32_t*)(ph1);
            ah[mt][2] = *(const uint32_t*)(ph0 + 8);
            ah[mt][3] = *(const uint32_t*)(ph1 + 8);
            al[mt][0] = *(const uint32_t*)(pl0);
            al[mt][1] = *(const uint32_t*)(pl1);
            al[mt][2] = *(const uint32_t*)(pl0 + 8);
            al[mt][3] = *(const uint32_t*)(pl1 + 8);
        }
        int koff = tap * 32 + (kc & 1) * 16 + tig * 2;
        // ---- B fragments in two halves of 4 n-tiles to bound register use
#pragma unroll
        for (int half = 0; half < 2; ++half) {
            uint32_t bh[4][2], bl[4][2];
#pragma unroll
            for (int q = 0; q < 4; ++q) {
                int nt = half * 4 + q;
                const __nv_bfloat16* pwh = g_WBhi + (d0 + nt * 8 + g) * 96 + koff;
                const __nv_bfloat16* pwl = g_WBlo + (d0 + nt * 8 + g) * 96 + koff;
                bh[q][0] = *(const uint32_t*)(pwh);
                bh[q][1] = *(const uint32_t*)(pwh + 8);
                bl[q][0] = *(const uint32_t*)(pwl);
                bl[q][1] = *(const uint32_t*)(pwl + 8);
            }
#pragma unroll
            for (int mt = 0; mt < 2; ++mt)
#pragma unroll
                for (int q = 0; q < 4; ++q) {
                    float* d = acc[mt][half * 4 + q];
                    mma16816(d[0], d[1], d[2], d[3],
                             ah[mt][0], ah[mt][1], ah[mt][2], ah[mt][3],
                             bh[q][0], bh[q][1]);
                    mma16816(d[0], d[1], d[2], d[3],
                             al[mt][0], al[mt][1], al[mt][2], al[mt][3],
                             bh[q][0], bh[q][1]);
                    mma16816(d[0], d[1], d[2], d[3],
                             ah[mt][0], ah[mt][1], ah[mt][2], ah[mt][3],
                             bl[q][0], bl[q][1]);
                }
        }
    }

    // ---- D regs -> smem (row-major, stride 68)
#pragma unroll
    for (int mt = 0; mt < 2; ++mt)
#pragma unroll
        for (int nt = 0; nt < 8; ++nt) {
            int row0 = w * 32 + mt * 16 + g;
            int col = nt * 8 + tig * 2;
            float2 v0; v0.x = acc[mt][nt][0]; v0.y = acc[mt][nt][1];
            float2 v1; v1.x = acc[mt][nt][2]; v1.y = acc[mt][nt][3];
            *(float2*)(sD + row0 * D_STRIDE + col) = v0;
            *(float2*)(sD + (row0 + 8) * D_STRIDE + col) = v1;
        }
    __syncthreads();

    // ---- epilogue: row m = tid, t = t0+m, 64 d columns
    {
        int t = t0 + tid;
        int cnt = sCnt;
        float af = (float)(32 - cnt) * (1.0f / 32.0f);
        float bf = (float)cnt * (1.0f / 32.0f);
        int4 xm = *(const int4*)(xmark + (b * 512 + t) * 4);
        const float* Tm = g_T + xm.x * 512 + d0;
        const float* Td = g_T + xm.y * 512 + d0;
        const float* Tw = g_T + xm.z * 512 + d0;
        const float* Th = g_T + xm.w * 512 + d0;
        const float* Tt = g_T + t * 512 + d0;
        const float* sp = sD + tid * D_STRIDE;
        float* op = out + (size_t)(b * 512 + t) * 512 + d0;
#pragma unroll
        for (int j = 0; j < 16; ++j) {
            int off = j * 4;
            float4 p4 = *(const float4*)(sp + off);
            float4 m4 = *(const float4*)(Tm + off);
            float4 d4 = *(const float4*)(Td + off);
            float4 w4 = *(const float4*)(Tw + off);
            float4 h4 = *(const float4*)(Th + off);
            float4 t4 = *(const float4*)(Tt + off);
            float4 r;
            r.x = p4.x + m4.x + d4.x + w4.x + h4.x + af * t4.x;
            r.y = p4.y + m4.y + d4.y + w4.y + h4.y + af * t4.y + bf;
            r.z = p4.z + m4.z + d4.z + w4.z + h4.z + af * t4.z;
            r.w = p4.w + m4.w + d4.w + w4.w + h4.w + af * t4.w + bf;
            *(float4*)(op + off) = r;
        }
    }
}

// ---------------- launch -----------------------------------------------------
extern "C" void kernel_launch(void* const* d_in, const int* in_sizes, int n_in,
                              void* d_out, int out_size) {
    const float* x      = (const float*)d_in[0];
    const int*   xmark  = (const int*)d_in[1];
    const float* conv_w = (const float*)d_in[2];
    float* out = (float*)d_out;

    setup_kernel<<<512, 256>>>(x, conv_w);
    dft_kernel<<<128, 256>>>(x);
    main_kernel<<<dim3(8, 4, 16), 128>>>(xmark, out);
}